// round 14
// baseline (speedup 1.0000x reference)
#include <cuda_runtime.h>
#include <math.h>

#define Bsz 2
#define Nn  2048
#define Dd  512
#define Hh  8
#define HDm 64
#define KK  64
#define Wcv 5
#define ROWS (Bsz*Nn)   // 4096
#define BH   (Bsz*Hh)   // 16

// ---------------- scratch (device globals; no allocation) ----------------
__device__ float g_Wq[Dd*Dd];
__device__ float g_Wk[Dd*Dd];
__device__ float g_ksum[ROWS*Dd];
__device__ float g_vcat[ROWS*2*Dd];
__device__ float g_q[ROWS*Dd];
__device__ float g_k[ROWS*Dd];
__device__ float g_v[ROWS*Dd];
__device__ float g_attn[ROWS*Dd];
__device__ float g_attnp[ROWS*Dd];
__device__ float g_ctx[ROWS*Dd];
__device__ float g_ctx2[ROWS*Dd];
__device__ float g_thr[ROWS];
__device__ int   g_order[ROWS];
__device__ float g_scores[(size_t)BH*Nn*Nn];   // 268 MB scratch

// ---------------- build Hamilton weight matrix Wm[o,d] ----------------
__global__ void build_w_kernel(const float* __restrict__ r, const float* __restrict__ i_,
                               const float* __restrict__ j_, const float* __restrict__ k_,
                               float* __restrict__ out) {
    int idx = blockIdx.x * blockDim.x + threadIdx.x;
    if (idx >= Dd * Dd) return;
    int o = idx >> 9, d = idx & 511;
    int bo = o >> 7, oo = o & 127, bd = d >> 7, dd = d & 127;
    const int cidx[4][4] = {{0,1,2,3},{1,0,3,2},{2,3,0,1},{3,2,1,0}};
    const float sgn[4][4] = {{1.f,-1.f,-1.f,-1.f},{1.f,1.f,-1.f,1.f},
                             {1.f,1.f,1.f,-1.f},{1.f,-1.f,1.f,1.f}};
    const float* comp[4] = {r, i_, j_, k_};
    out[idx] = sgn[bo][bd] * comp[cidx[bo][bd]][oo * 128 + dd];
}

// ---------------- prep: ksum = key+cross ; vcat = [value|cross] ----------------
__global__ void prep_kernel(const float* __restrict__ key, const float* __restrict__ cross,
                            const float* __restrict__ value) {
    for (int i = blockIdx.x * blockDim.x + threadIdx.x; i < ROWS * Dd;
         i += gridDim.x * blockDim.x) {
        g_ksum[i] = key[i] + cross[i];
        int row = i >> 9, col = i & 511;
        g_vcat[row * 1024 + col]       = value[i];
        g_vcat[row * 1024 + 512 + col] = cross[i];
    }
}

// ---------------- threshold (density MLP + softplus(thr)) ----------------
__global__ void thr_kernel(const float* __restrict__ df,
                           const float* __restrict__ dm1w, const float* __restrict__ dm1b,
                           const float* __restrict__ dm2w, const float* __restrict__ dm2b,
                           const float* __restrict__ thr) {
    int i = blockIdx.x * blockDim.x + threadIdx.x;
    if (i >= ROWS) return;
    float x0 = df[i*3], x1 = df[i*3+1], x2 = df[i*3+2];
    float base = log1pf(expf(thr[0]));
    float acc = dm2b[0];
    for (int h = 0; h < 16; h++) {
        float v = dm1w[h*3]*x0 + dm1w[h*3+1]*x1 + dm1w[h*3+2]*x2 + dm1b[h];
        float g = 0.5f * v * (1.f + erff(v * 0.7071067811865475f));
        acc += dm2w[h] * g;
    }
    g_thr[i] = base + 0.1f * acc;
}

// ---------------- stable argsort per batch: exact rank by counting ----------------
__global__ void sort_kernel(const int* __restrict__ time_idx) {
    __shared__ int tk[Nn];
    int b = blockIdx.x;
    int t = threadIdx.x;                 // 1024 threads
    for (int i = t; i < Nn; i += 1024) tk[i] = time_idx[b * Nn + i];
    __syncthreads();
    for (int i = t; i < Nn; i += 1024) {
        int ti = tk[i];
        int rank = 0;
        for (int j = 0; j < Nn; j++) {
            int tj = tk[j];
            rank += (tj < ti) || (tj == ti && j < i);
        }
        g_order[b * Nn + rank] = i;      // sorted position 'rank' holds original index i
    }
}

// ---------------- tiled fp32 GEMM: C[M,N] = A[M,K] @ W[N,K]^T + biasScale*bias ----------------
__global__ void gemm_kernel(const float* __restrict__ A, const float* __restrict__ W,
                            const float* __restrict__ bias, float biasScale,
                            float* __restrict__ C, int M, int Nout, int Kin) {
    __shared__ float As[16][64];
    __shared__ float Bs[16][64];
    int tid = threadIdx.x;              // 256
    int tx = tid & 15, ty = tid >> 4;
    int m0 = blockIdx.y * 64, n0 = blockIdx.x * 64;
    int lr = tid >> 2;                  // 0..63
    int lk = (tid & 3) * 4;             // 0,4,8,12
    float acc[4][4];
    #pragma unroll
    for (int i = 0; i < 4; i++)
        #pragma unroll
        for (int j = 0; j < 4; j++) acc[i][j] = 0.f;

    for (int k0 = 0; k0 < Kin; k0 += 16) {
        float4 av = *(const float4*)&A[(size_t)(m0 + lr) * Kin + k0 + lk];
        float4 wv = *(const float4*)&W[(size_t)(n0 + lr) * Kin + k0 + lk];
        As[lk  ][lr] = av.x; As[lk+1][lr] = av.y; As[lk+2][lr] = av.z; As[lk+3][lr] = av.w;
        Bs[lk  ][lr] = wv.x; Bs[lk+1][lr] = wv.y; Bs[lk+2][lr] = wv.z; Bs[lk+3][lr] = wv.w;
        __syncthreads();
        #pragma unroll
        for (int kk = 0; kk < 16; kk++) {
            float4 a4 = *(const float4*)&As[kk][ty * 4];
            float4 b4 = *(const float4*)&Bs[kk][tx * 4];
            float a[4] = {a4.x, a4.y, a4.z, a4.w};
            float b[4] = {b4.x, b4.y, b4.z, b4.w};
            #pragma unroll
            for (int i = 0; i < 4; i++)
                #pragma unroll
                for (int j = 0; j < 4; j++) acc[i][j] += a[i] * b[j];
        }
        __syncthreads();
    }
    #pragma unroll
    for (int i = 0; i < 4; i++) {
        int m = m0 + ty * 4 + i;
        #pragma unroll
        for (int j = 0; j < 4; j++) {
            int n = n0 + tx * 4 + j;
            float bv = bias ? bias[n] * biasScale : 0.f;
            C[(size_t)m * Nout + n] = acc[i][j] + bv;
        }
    }
}

// ---------------- scores: mod[b,h,m,n] (gate/mask/clip applied), materialized ----------------
__global__ void scores_kernel(const float* __restrict__ mask) {
    __shared__ float Qs[64][68];
    __shared__ float Ks[64][68];
    __shared__ float Tn[64];
    __shared__ float Mm[64];
    __shared__ float Mn[64];
    int bh = blockIdx.z, b = bh >> 3, h = bh & 7;
    int m0 = blockIdx.y * 64, n0 = blockIdx.x * 64;
    int tid = threadIdx.x;
    int tx = tid & 15, ty = tid >> 4;

    for (int idx = tid; idx < 64 * 16; idx += 256) {
        int row = idx >> 4, c4 = (idx & 15) * 4;
        *(float4*)&Qs[row][c4] = *(const float4*)&g_q[(size_t)(b * Nn + m0 + row) * Dd + h * HDm + c4];
        *(float4*)&Ks[row][c4] = *(const float4*)&g_k[(size_t)(b * Nn + n0 + row) * Dd + h * HDm + c4];
    }
    if (tid < 64) {
        Tn[tid] = g_thr[b * Nn + n0 + tid];
        Mm[tid] = mask[b * Nn + m0 + tid];
        Mn[tid] = mask[b * Nn + n0 + tid];
    }
    __syncthreads();

    float s[4][4];
    #pragma unroll
    for (int i = 0; i < 4; i++)
        #pragma unroll
        for (int j = 0; j < 4; j++) s[i][j] = 0.f;
    for (int k4 = 0; k4 < 64; k4 += 4) {
        float4 qa[4], kb[4];
        #pragma unroll
        for (int i = 0; i < 4; i++) qa[i] = *(const float4*)&Qs[ty * 4 + i][k4];
        #pragma unroll
        for (int j = 0; j < 4; j++) kb[j] = *(const float4*)&Ks[tx * 4 + j][k4];
        #pragma unroll
        for (int i = 0; i < 4; i++)
            #pragma unroll
            for (int j = 0; j < 4; j++)
                s[i][j] += qa[i].x*kb[j].x + qa[i].y*kb[j].y + qa[i].z*kb[j].z + qa[i].w*kb[j].w;
    }

    #pragma unroll
    for (int i = 0; i < 4; i++) {
        float mm = Mm[ty * 4 + i];
        #pragma unroll
        for (int j = 0; j < 4; j++) {
            float sc = s[i][j] * 0.25f;               // / sqrt(QC=16)
            sc = fminf(6.f, fmaxf(-6.f, sc));
            float t = Tn[tx * 4 + j];
            float gate = 1.f / (1.f + __expf(-5.f * (sc - t)));
            float mod = sc * (1.f + 2.f * gate);
            if (mm * Mn[tx * 4 + j] == 0.f) mod = -10000.f;
            mod = fminf(30.f, fmaxf(-30.f, mod));
            g_scores[((size_t)bh * Nn + m0 + ty * 4 + i) * Nn + n0 + tx * 4 + j] = mod;
        }
    }
}

// ---------------- row softmax over n (in place) ----------------
__global__ void softmax_kernel() {
    __shared__ float red[256];
    size_t base = (size_t)blockIdx.x * Nn;
    int tid = threadIdx.x;

    float mx = -1e30f;
    for (int j = tid; j < Nn; j += 256) mx = fmaxf(mx, g_scores[base + j]);
    red[tid] = mx; __syncthreads();
    for (int s = 128; s; s >>= 1) { if (tid < s) red[tid] = fmaxf(red[tid], red[tid + s]); __syncthreads(); }
    mx = red[0];
    __syncthreads();

    float sum = 0.f;
    for (int j = tid; j < Nn; j += 256) {
        float e = __expf(g_scores[base + j] - mx);
        g_scores[base + j] = e;
        sum += e;
    }
    red[tid] = sum; __syncthreads();
    for (int s = 128; s; s >>= 1) { if (tid < s) red[tid] += red[tid + s]; __syncthreads(); }
    float inv = 1.f / red[0];
    for (int j = tid; j < Nn; j += 256) g_scores[base + j] *= inv;
}

// ---------------- attn = wts @ vh ----------------
__global__ void pv_kernel() {
    __shared__ float Ws[64][20];
    __shared__ float Vs[16][68];
    int bh = blockIdx.y, b = bh >> 3, h = bh & 7;
    int m0 = blockIdx.x * 64;
    int tid = threadIdx.x;
    int tx = tid & 15, ty = tid >> 4;

    float acc[4][4];
    #pragma unroll
    for (int i = 0; i < 4; i++)
        #pragma unroll
        for (int j = 0; j < 4; j++) acc[i][j] = 0.f;

    for (int n0 = 0; n0 < Nn; n0 += 16) {
        __syncthreads();
        {
            int row = tid >> 2, c4 = (tid & 3) * 4;
            *(float4*)&Ws[row][c4] =
                *(const float4*)&g_scores[((size_t)bh * Nn + m0 + row) * Nn + n0 + c4];
        }
        {
            int vr = tid >> 4, c4 = (tid & 15) * 4;
            *(float4*)&Vs[vr][c4] =
                *(const float4*)&g_v[(size_t)(b * Nn + n0 + vr) * Dd + h * HDm + c4];
        }
        __syncthreads();
        #pragma unroll
        for (int kk = 0; kk < 16; kk++) {
            float w0 = Ws[ty * 4 + 0][kk], w1 = Ws[ty * 4 + 1][kk];
            float w2 = Ws[ty * 4 + 2][kk], w3 = Ws[ty * 4 + 3][kk];
            float4 v4 = *(const float4*)&Vs[kk][tx * 4];
            acc[0][0] += w0 * v4.x; acc[0][1] += w0 * v4.y; acc[0][2] += w0 * v4.z; acc[0][3] += w0 * v4.w;
            acc[1][0] += w1 * v4.x; acc[1][1] += w1 * v4.y; acc[1][2] += w1 * v4.z; acc[1][3] += w1 * v4.w;
            acc[2][0] += w2 * v4.x; acc[2][1] += w2 * v4.y; acc[2][2] += w2 * v4.z; acc[2][3] += w2 * v4.w;
            acc[3][0] += w3 * v4.x; acc[3][1] += w3 * v4.y; acc[3][2] += w3 * v4.z; acc[3][3] += w3 * v4.w;
        }
    }
    #pragma unroll
    for (int i = 0; i < 4; i++)
        #pragma unroll
        for (int j = 0; j < 4; j++)
            g_attn[(size_t)(b * Nn + m0 + ty * 4 + i) * Dd + h * HDm + tx * 4 + j] = acc[i][j];
}

// ---------------- temporal event conv: K=64 kernels, W=5 window ----------------
// grid: ROWS blocks (b,j in sorted domain) x 256 threads
__global__ void event_kernel(const float* __restrict__ query, const float* __restrict__ mask,
                             const float* __restrict__ ef, const float* __restrict__ ec) {
    __shared__ float qwin[Wcv * Dd];   // 2560 floats
    __shared__ float red[256];
    __shared__ float wk[KK];
    __shared__ float s_inv;
    int b = blockIdx.x >> 11;
    int j = blockIdx.x & 2047;
    int tid = threadIdx.x;   // 256

    #pragma unroll
    for (int w = 0; w < Wcv; w++) {
        int src = j + w - 2;
        int row = (src >= 0 && src < Nn) ? g_order[b * Nn + src] : -1;
        for (int d = tid; d < Dd; d += 256)
            qwin[w * Dd + d] = (row >= 0) ? query[((size_t)(b * Nn + row)) * Dd + d] : 0.f;
    }
    int dest = g_order[b * Nn + j];
    float msj = mask[b * Nn + dest];
    __syncthreads();

    // 4 threads per kernel: k = tid/4, strided partial dot over 2560 elems
    int k = tid >> 2, s = tid & 3;
    float p = 0.f;
    const float* fk = &ef[(size_t)k * (Wcv * Dd)];
    for (int e = s; e < Wcv * Dd; e += 4) p += qwin[e] * fk[e];
    red[tid] = p;
    __syncthreads();
    if (tid < KK) {
        float a = (red[tid*4] + red[tid*4+1] + red[tid*4+2] + red[tid*4+3])
                  * 0.08838834764831845f;                 // 1/sqrt(QI=128)
        if (msj == 0.f) a = -10000.f;
        wk[tid] = a;
    }
    __syncthreads();
    if (tid == 0) {
        float mx = -1e30f;
        for (int kk = 0; kk < KK; kk++) mx = fmaxf(mx, wk[kk]);
        float sum = 0.f;
        for (int kk = 0; kk < KK; kk++) { float e = __expf(wk[kk] - mx); wk[kk] = e; sum += e; }
        s_inv = 1.f / sum;
    }
    __syncthreads();
    float inv = s_inv;
    for (int d = tid; d < Dd; d += 256) {
        float v = 0.f;
        #pragma unroll 8
        for (int kk = 0; kk < KK; kk++) v += wk[kk] * ec[kk * Dd + d];
        g_ctx[((size_t)(b * Nn + dest)) * Dd + d] = v * inv;
    }
}

// ---------------- layernorm(ctx2)*mask^2 + attn_proj -> out ----------------
__global__ void final_kernel(const float* __restrict__ mask, const float* __restrict__ ln_g,
                             const float* __restrict__ ln_b, float* __restrict__ out) {
    __shared__ float red[256];
    __shared__ float s_mean, s_rstd;
    int row = blockIdx.x;          // 4096
    int tid = threadIdx.x;         // 256
    const float* x = &g_ctx2[(size_t)row * Dd];

    red[tid] = x[tid] + x[tid + 256]; __syncthreads();
    for (int s = 128; s; s >>= 1) { if (tid < s) red[tid] += red[tid + s]; __syncthreads(); }
    if (tid == 0) s_mean = red[0] * (1.f / Dd);
    __syncthreads();
    float mean = s_mean;
    float d0 = x[tid] - mean, d1 = x[tid + 256] - mean;
    __syncthreads();
    red[tid] = d0 * d0 + d1 * d1; __syncthreads();
    for (int s = 128; s; s >>= 1) { if (tid < s) red[tid] += red[tid + s]; __syncthreads(); }
    if (tid == 0) s_rstd = rsqrtf(red[0] * (1.f / Dd) + 1e-5f);
    __syncthreads();
    float rstd = s_rstd;
    float m = mask[row];
    float mm = m * m;
    for (int r = 0; r < 2; r++) {
        int d = tid + r * 256;
        float nv = (x[d] - mean) * rstd * ln_g[d] + ln_b[d];
        out[(size_t)row * Dd + d] = g_attnp[(size_t)row * Dd + d] + nv * mm;
    }
}

// ---------------- launch (dict order; sizes verified: K=64 -> ef 163840, ec 32768) ----
extern "C" void kernel_launch(void* const* d_in, const int* in_sizes, int n_in,
                              void* d_out, int out_size) {
    const float* query  = (const float*)d_in[0];
    const float* key    = (const float*)d_in[1];
    const float* value  = (const float*)d_in[2];
    const float* cross  = (const float*)d_in[3];
    const float* df     = (const float*)d_in[4];
    const float* mask   = (const float*)d_in[5];
    const int*   t_idx  = (const int*)  d_in[6];
    const float* q_r = (const float*)d_in[7],  *q_i = (const float*)d_in[8];
    const float* q_j = (const float*)d_in[9],  *q_k = (const float*)d_in[10];
    const float* q_b = (const float*)d_in[11];
    const float* k_r = (const float*)d_in[12], *k_i = (const float*)d_in[13];
    const float* k_j = (const float*)d_in[14], *k_k = (const float*)d_in[15];
    const float* k_b = (const float*)d_in[16];
    const float* v_w = (const float*)d_in[17], *v_b = (const float*)d_in[18];
    const float* o_w = (const float*)d_in[19], *o_b = (const float*)d_in[20];
    const float* thr = (const float*)d_in[21];
    const float* dm1_w = (const float*)d_in[22], *dm1_b = (const float*)d_in[23];
    const float* dm2_w = (const float*)d_in[24], *dm2_b = (const float*)d_in[25];
    const float* ef  = (const float*)d_in[26], *ec  = (const float*)d_in[27];
    const float* ev_w = (const float*)d_in[28], *ev_b = (const float*)d_in[29];
    const float* ln_g = (const float*)d_in[30], *ln_b = (const float*)d_in[31];
    float* out = (float*)d_out;

    float *pWq, *pWk, *pKsum, *pVcat, *pQ, *pK, *pV, *pAttn, *pAttnP, *pCtx, *pCtx2;
    cudaGetSymbolAddress((void**)&pWq,   g_Wq);
    cudaGetSymbolAddress((void**)&pWk,   g_Wk);
    cudaGetSymbolAddress((void**)&pKsum, g_ksum);
    cudaGetSymbolAddress((void**)&pVcat, g_vcat);
    cudaGetSymbolAddress((void**)&pQ,    g_q);
    cudaGetSymbolAddress((void**)&pK,    g_k);
    cudaGetSymbolAddress((void**)&pV,    g_v);
    cudaGetSymbolAddress((void**)&pAttn, g_attn);
    cudaGetSymbolAddress((void**)&pAttnP,g_attnp);
    cudaGetSymbolAddress((void**)&pCtx,  g_ctx);
    cudaGetSymbolAddress((void**)&pCtx2, g_ctx2);

    // weights + prep + threshold + sort
    build_w_kernel<<<(Dd*Dd + 255) / 256, 256>>>(q_r, q_i, q_j, q_k, pWq);
    build_w_kernel<<<(Dd*Dd + 255) / 256, 256>>>(k_r, k_i, k_j, k_k, pWk);
    prep_kernel<<<2048, 256>>>(key, cross, value);
    thr_kernel<<<(ROWS + 255) / 256, 256>>>(df, dm1_w, dm1_b, dm2_w, dm2_b, thr);
    sort_kernel<<<Bsz, 1024>>>(t_idx);

    // projections
    dim3 g512(Dd / 64, ROWS / 64);
    gemm_kernel<<<g512, 256>>>(query, pWq, q_b, 1.f, pQ, ROWS, Dd, Dd);
    gemm_kernel<<<g512, 256>>>(pKsum, pWk, k_b, 2.f, pK, ROWS, Dd, Dd);
    gemm_kernel<<<g512, 256>>>(pVcat, v_w, v_b, 1.f, pV, ROWS, Dd, 2 * Dd);

    // attention: materialized scores -> softmax -> PV
    dim3 gs(Nn / 64, Nn / 64, BH);
    scores_kernel<<<gs, 256>>>(mask);
    softmax_kernel<<<BH * Nn, 256>>>();
    pv_kernel<<<dim3(Nn / 64, BH), 256>>>();
    gemm_kernel<<<g512, 256>>>(pAttn, o_w, o_b, 1.f, pAttnP, ROWS, Dd, Dd);

    // event conv (K=64) + event value projection
    event_kernel<<<ROWS, 256>>>(query, mask, ef, ec);
    gemm_kernel<<<g512, 256>>>(pCtx, ev_w, ev_b, 1.f, pCtx2, ROWS, Dd, Dd);

    // layernorm + combine
    final_kernel<<<ROWS, 256>>>(mask, ln_g, ln_b, out);
}

// round 15
// speedup vs baseline: 1.3009x; 1.3009x over previous
#include <cuda_runtime.h>
#include <math.h>

#define Bsz 2
#define Nn  2048
#define Dd  512
#define Hh  8
#define HDm 64
#define KK  64
#define Wcv 5
#define ROWS (Bsz*Nn)   // 4096
#define BH   (Bsz*Hh)   // 16

// ---------------- scratch (device globals; no allocation) ----------------
__device__ float g_Wq[Dd*Dd];
__device__ float g_Wk[Dd*Dd];
__device__ float g_ksum[ROWS*Dd];
__device__ float g_vcat[ROWS*2*Dd];
__device__ float g_q[ROWS*Dd];
__device__ float g_k[ROWS*Dd];
__device__ float g_v[ROWS*Dd];
__device__ float g_attn[ROWS*Dd];
__device__ float g_attnp[ROWS*Dd];
__device__ float g_ctx[ROWS*Dd];
__device__ float g_ctx2[ROWS*Dd];
__device__ float g_thr[ROWS];
__device__ int   g_order[ROWS];

// ---------------- build Hamilton weight matrix Wm[o,d] ----------------
__global__ void build_w_kernel(const float* __restrict__ r, const float* __restrict__ i_,
                               const float* __restrict__ j_, const float* __restrict__ k_,
                               float* __restrict__ out) {
    int idx = blockIdx.x * blockDim.x + threadIdx.x;
    if (idx >= Dd * Dd) return;
    int o = idx >> 9, d = idx & 511;
    int bo = o >> 7, oo = o & 127, bd = d >> 7, dd = d & 127;
    const int cidx[4][4] = {{0,1,2,3},{1,0,3,2},{2,3,0,1},{3,2,1,0}};
    const float sgn[4][4] = {{1.f,-1.f,-1.f,-1.f},{1.f,1.f,-1.f,1.f},
                             {1.f,1.f,1.f,-1.f},{1.f,-1.f,1.f,1.f}};
    const float* comp[4] = {r, i_, j_, k_};
    out[idx] = sgn[bo][bd] * comp[cidx[bo][bd]][oo * 128 + dd];
}

// ---------------- prep: ksum = key+cross ; vcat = [value|cross] ----------------
__global__ void prep_kernel(const float* __restrict__ key, const float* __restrict__ cross,
                            const float* __restrict__ value) {
    for (int i = blockIdx.x * blockDim.x + threadIdx.x; i < ROWS * Dd;
         i += gridDim.x * blockDim.x) {
        g_ksum[i] = key[i] + cross[i];
        int row = i >> 9, col = i & 511;
        g_vcat[row * 1024 + col]       = value[i];
        g_vcat[row * 1024 + 512 + col] = cross[i];
    }
}

// ---------------- threshold (density MLP + softplus(thr)) ----------------
__global__ void thr_kernel(const float* __restrict__ df,
                           const float* __restrict__ dm1w, const float* __restrict__ dm1b,
                           const float* __restrict__ dm2w, const float* __restrict__ dm2b,
                           const float* __restrict__ thr) {
    int i = blockIdx.x * blockDim.x + threadIdx.x;
    if (i >= ROWS) return;
    float x0 = df[i*3], x1 = df[i*3+1], x2 = df[i*3+2];
    float base = log1pf(expf(thr[0]));
    float acc = dm2b[0];
    for (int h = 0; h < 16; h++) {
        float v = dm1w[h*3]*x0 + dm1w[h*3+1]*x1 + dm1w[h*3+2]*x2 + dm1b[h];
        float g = 0.5f * v * (1.f + erff(v * 0.7071067811865475f));
        acc += dm2w[h] * g;
    }
    g_thr[i] = base + 0.1f * acc;
}

// ---------------- stable argsort per batch: exact rank by counting ----------------
__global__ void sort_kernel(const int* __restrict__ time_idx) {
    __shared__ int tk[Nn];
    int b = blockIdx.x;
    int t = threadIdx.x;                 // 1024 threads
    for (int i = t; i < Nn; i += 1024) tk[i] = time_idx[b * Nn + i];
    __syncthreads();
    for (int i = t; i < Nn; i += 1024) {
        int ti = tk[i];
        int rank = 0;
        for (int j = 0; j < Nn; j++) {
            int tj = tk[j];
            rank += (tj < ti) || (tj == ti && j < i);
        }
        g_order[b * Nn + rank] = i;
    }
}

// ---------------- SGEMM 128x128x8, 8x8 microtile: C = A @ W^T + bs*bias ----------------
// grid (Nout/128, M/128), 256 threads. M,Nout multiples of 128; Kin multiple of 8.
__global__ void gemm128_kernel(const float* __restrict__ A, const float* __restrict__ W,
                               const float* __restrict__ bias, float biasScale,
                               float* __restrict__ C, int M, int Nout, int Kin) {
    __shared__ float As[8][128];
    __shared__ float Bs[8][128];
    int tid = threadIdx.x;
    int tx = tid & 15, ty = tid >> 4;
    int m0 = blockIdx.y * 128, n0 = blockIdx.x * 128;
    int lr = tid >> 1;              // 0..127
    int lk = (tid & 1) * 4;         // 0 or 4

    float acc[8][8];
    #pragma unroll
    for (int i = 0; i < 8; i++)
        #pragma unroll
        for (int j = 0; j < 8; j++) acc[i][j] = 0.f;

    for (int k0 = 0; k0 < Kin; k0 += 8) {
        float4 av = *(const float4*)&A[(size_t)(m0 + lr) * Kin + k0 + lk];
        float4 wv = *(const float4*)&W[(size_t)(n0 + lr) * Kin + k0 + lk];
        As[lk  ][lr] = av.x; As[lk+1][lr] = av.y; As[lk+2][lr] = av.z; As[lk+3][lr] = av.w;
        Bs[lk  ][lr] = wv.x; Bs[lk+1][lr] = wv.y; Bs[lk+2][lr] = wv.z; Bs[lk+3][lr] = wv.w;
        __syncthreads();
        #pragma unroll
        for (int kk = 0; kk < 8; kk++) {
            float a[8], b[8];
            *(float4*)&a[0] = *(const float4*)&As[kk][ty * 8];
            *(float4*)&a[4] = *(const float4*)&As[kk][ty * 8 + 4];
            *(float4*)&b[0] = *(const float4*)&Bs[kk][tx * 8];
            *(float4*)&b[4] = *(const float4*)&Bs[kk][tx * 8 + 4];
            #pragma unroll
            for (int i = 0; i < 8; i++)
                #pragma unroll
                for (int j = 0; j < 8; j++) acc[i][j] += a[i] * b[j];
        }
        __syncthreads();
    }
    #pragma unroll
    for (int i = 0; i < 8; i++) {
        int m = m0 + ty * 8 + i;
        #pragma unroll
        for (int j = 0; j < 8; j += 4) {
            int n = n0 + tx * 8 + j;
            float4 o;
            o.x = acc[i][j  ] + (bias ? bias[n  ] * biasScale : 0.f);
            o.y = acc[i][j+1] + (bias ? bias[n+1] * biasScale : 0.f);
            o.z = acc[i][j+2] + (bias ? bias[n+2] * biasScale : 0.f);
            o.w = acc[i][j+3] + (bias ? bias[n+3] * biasScale : 0.f);
            *(float4*)&C[(size_t)m * Nout + n] = o;
        }
    }
}

// ---------------- flash-style spike attention (cross-validated in R1/R2) ----------------
// grid: B*H*(N/64) = 512 blocks of 256 threads; dynamic smem
__global__ void attn_kernel(const float* __restrict__ mask) {
    extern __shared__ float sm[];
    float* Qs = sm;                 // 64*68
    float* Ks = Qs + 64 * 68;
    float* Vs = Ks + 64 * 68;
    float* Ps = Vs + 64 * 68;
    float* Ts = Ps + 64 * 68;       // 64
    float* Mn = Ts + 64;            // 64
    float* Mq = Mn + 64;            // 64

    int bid = blockIdx.x;
    int mt = bid & 31;
    int h  = (bid >> 5) & 7;
    int b  = bid >> 8;
    int m0 = mt * 64;
    int tid = threadIdx.x;
    int tx = tid & 15, ty = tid >> 4;

    #pragma unroll
    for (int rep = 0; rep < 4; rep++) {
        int row = rep * 16 + ty;
        float4 v = *(const float4*)&g_q[((size_t)(b * Nn + m0 + row)) * Dd + h * HDm + tx * 4];
        *(float4*)&Qs[row * 68 + tx * 4] = v;
    }
    if (tid < 64) Mq[tid] = mask[b * Nn + m0 + tid];

    float mrow[4], lrow[4], acc[4][4];
    #pragma unroll
    for (int i = 0; i < 4; i++) {
        mrow[i] = -1e30f; lrow[i] = 0.f;
        #pragma unroll
        for (int j = 0; j < 4; j++) acc[i][j] = 0.f;
    }

    for (int nt = 0; nt < Nn / 64; nt++) {
        int n0 = nt * 64;
        __syncthreads();
        #pragma unroll
        for (int rep = 0; rep < 4; rep++) {
            int row = rep * 16 + ty;
            size_t base = ((size_t)(b * Nn + n0 + row)) * Dd + h * HDm + tx * 4;
            *(float4*)&Ks[row * 68 + tx * 4] = *(const float4*)&g_k[base];
            *(float4*)&Vs[row * 68 + tx * 4] = *(const float4*)&g_v[base];
        }
        if (tid < 64) {
            Ts[tid] = g_thr[b * Nn + n0 + tid];
            Mn[tid] = mask[b * Nn + n0 + tid];
        }
        __syncthreads();

        float s[4][4];
        #pragma unroll
        for (int i = 0; i < 4; i++)
            #pragma unroll
            for (int j = 0; j < 4; j++) s[i][j] = 0.f;
        for (int k4 = 0; k4 < 64; k4 += 4) {
            float4 qa[4], kb[4];
            #pragma unroll
            for (int i = 0; i < 4; i++) qa[i] = *(const float4*)&Qs[(ty * 4 + i) * 68 + k4];
            #pragma unroll
            for (int j = 0; j < 4; j++) kb[j] = *(const float4*)&Ks[(tx * 4 + j) * 68 + k4];
            #pragma unroll
            for (int i = 0; i < 4; i++)
                #pragma unroll
                for (int j = 0; j < 4; j++)
                    s[i][j] += qa[i].x*kb[j].x + qa[i].y*kb[j].y + qa[i].z*kb[j].z + qa[i].w*kb[j].w;
        }

        float mq[4];
        #pragma unroll
        for (int i = 0; i < 4; i++) mq[i] = Mq[ty * 4 + i];

        float p[4][4], rowmax[4];
        #pragma unroll
        for (int i = 0; i < 4; i++) {
            rowmax[i] = -1e30f;
            #pragma unroll
            for (int j = 0; j < 4; j++) {
                float sc = s[i][j] * 0.25f;
                sc = fminf(6.f, fmaxf(-6.f, sc));
                float t = Ts[tx * 4 + j];
                float gate = 1.f / (1.f + __expf(-5.f * (sc - t)));
                float mod = sc * (1.f + 2.f * gate);
                if (mq[i] * Mn[tx * 4 + j] == 0.f) mod = -10000.f;
                mod = fminf(30.f, fmaxf(-30.f, mod));
                p[i][j] = mod;
                rowmax[i] = fmaxf(rowmax[i], mod);
            }
        }
        #pragma unroll
        for (int off = 8; off; off >>= 1)
            #pragma unroll
            for (int i = 0; i < 4; i++)
                rowmax[i] = fmaxf(rowmax[i], __shfl_xor_sync(0xffffffffu, rowmax[i], off));

        float rs[4];
        #pragma unroll
        for (int i = 0; i < 4; i++) {
            float mnew = fmaxf(mrow[i], rowmax[i]);
            float scale = __expf(mrow[i] - mnew);
            mrow[i] = mnew;
            lrow[i] *= scale;
            float sum = 0.f;
            #pragma unroll
            for (int j = 0; j < 4; j++) {
                float e = __expf(p[i][j] - mnew);
                p[i][j] = e; sum += e;
            }
            rs[i] = sum;
            #pragma unroll
            for (int j = 0; j < 4; j++) acc[i][j] *= scale;
        }
        #pragma unroll
        for (int off = 8; off; off >>= 1)
            #pragma unroll
            for (int i = 0; i < 4; i++)
                rs[i] += __shfl_xor_sync(0xffffffffu, rs[i], off);
        #pragma unroll
        for (int i = 0; i < 4; i++) lrow[i] += rs[i];

        #pragma unroll
        for (int i = 0; i < 4; i++)
            *(float4*)&Ps[(ty * 4 + i) * 68 + tx * 4] = make_float4(p[i][0], p[i][1], p[i][2], p[i][3]);
        __syncthreads();

        for (int c = 0; c < 64; c++) {
            float4 v4 = *(const float4*)&Vs[c * 68 + tx * 4];
            #pragma unroll
            for (int i = 0; i < 4; i++) {
                float pv = Ps[(ty * 4 + i) * 68 + c];
                acc[i][0] += pv * v4.x; acc[i][1] += pv * v4.y;
                acc[i][2] += pv * v4.z; acc[i][3] += pv * v4.w;
            }
        }
    }

    #pragma unroll
    for (int i = 0; i < 4; i++) {
        float inv = 1.f / lrow[i];
        #pragma unroll
        for (int j = 0; j < 4; j++)
            g_attn[((size_t)(b * Nn + m0 + ty * 4 + i)) * Dd + h * HDm + tx * 4 + j] = acc[i][j] * inv;
    }
}

// ---------------- temporal event conv: K=64, W=5, 8 sorted rows per block ----------------
// grid: ROWS/8 = 512 blocks, 256 threads
__global__ void event_kernel(const float* __restrict__ query, const float* __restrict__ mask,
                             const float* __restrict__ ef, const float* __restrict__ ec) {
    __shared__ float sbuf[12 * Dd];       // rows j0-2 .. j0+9  (24 KB)
    __shared__ float red[256][8];         // partial dots       (8 KB)
    __shared__ float wk[KK][8];           // softmax weights
    __shared__ float s_inv[8];
    __shared__ int   s_dest[8];
    __shared__ float s_msk[8];
    int blk = blockIdx.x;
    int b = blk >> 8;                     // ROWS/8 = 512 -> 256 j-tiles per batch
    int jt = blk & 255;
    int j0 = jt * 8;
    int tid = threadIdx.x;

    #pragma unroll
    for (int r = 0; r < 12; r++) {
        int src = j0 + r - 2;
        int row = (src >= 0 && src < Nn) ? g_order[b * Nn + src] : -1;
        for (int d = tid; d < Dd; d += 256)
            sbuf[r * Dd + d] = (row >= 0) ? query[((size_t)(b * Nn + row)) * Dd + d] : 0.f;
    }
    if (tid < 8) {
        int dest = g_order[b * Nn + j0 + tid];
        s_dest[tid] = dest;
        s_msk[tid] = mask[b * Nn + dest];
    }
    __syncthreads();

    // thread (k = tid/4, s = tid%4): partial dot for all 8 jj, ef element reused 8x
    {
        int k = tid >> 2, s = tid & 3;
        float acc[8] = {0.f,0.f,0.f,0.f,0.f,0.f,0.f,0.f};
        const float* fk = &ef[(size_t)k * (Wcv * Dd)];
        for (int e = s; e < Wcv * Dd; e += 4) {
            float fv = fk[e];
            #pragma unroll
            for (int jj = 0; jj < 8; jj++) acc[jj] += sbuf[jj * Dd + e] * fv;
        }
        #pragma unroll
        for (int jj = 0; jj < 8; jj++) red[tid][jj] = acc[jj];
    }
    __syncthreads();
    if (tid < KK) {
        #pragma unroll
        for (int jj = 0; jj < 8; jj++) {
            float a = (red[tid*4][jj] + red[tid*4+1][jj] + red[tid*4+2][jj] + red[tid*4+3][jj])
                      * 0.08838834764831845f;             // 1/sqrt(QI=128)
            if (s_msk[jj] == 0.f) a = -10000.f;
            wk[tid][jj] = a;
        }
    }
    __syncthreads();
    if (tid < 8) {
        float mx = -1e30f;
        for (int k = 0; k < KK; k++) mx = fmaxf(mx, wk[k][tid]);
        float sum = 0.f;
        for (int k = 0; k < KK; k++) { float e = __expf(wk[k][tid] - mx); wk[k][tid] = e; sum += e; }
        s_inv[tid] = 1.f / sum;
    }
    __syncthreads();

    for (int d = tid; d < Dd; d += 256) {
        float acc[8] = {0.f,0.f,0.f,0.f,0.f,0.f,0.f,0.f};
        for (int k = 0; k < KK; k++) {
            float ecv = ec[k * Dd + d];
            #pragma unroll
            for (int jj = 0; jj < 8; jj++) acc[jj] += wk[k][jj] * ecv;
        }
        #pragma unroll
        for (int jj = 0; jj < 8; jj++)
            g_ctx[((size_t)(b * Nn + s_dest[jj])) * Dd + d] = acc[jj] * s_inv[jj];
    }
}

// ---------------- layernorm(ctx2)*mask^2 + attn_proj -> out ----------------
__global__ void final_kernel(const float* __restrict__ mask, const float* __restrict__ ln_g,
                             const float* __restrict__ ln_b, float* __restrict__ out) {
    __shared__ float red[256];
    __shared__ float s_mean, s_rstd;
    int row = blockIdx.x;          // 4096
    int tid = threadIdx.x;         // 256
    const float* x = &g_ctx2[(size_t)row * Dd];

    red[tid] = x[tid] + x[tid + 256]; __syncthreads();
    for (int s = 128; s; s >>= 1) { if (tid < s) red[tid] += red[tid + s]; __syncthreads(); }
    if (tid == 0) s_mean = red[0] * (1.f / Dd);
    __syncthreads();
    float mean = s_mean;
    float d0 = x[tid] - mean, d1 = x[tid + 256] - mean;
    __syncthreads();
    red[tid] = d0 * d0 + d1 * d1; __syncthreads();
    for (int s = 128; s; s >>= 1) { if (tid < s) red[tid] += red[tid + s]; __syncthreads(); }
    if (tid == 0) s_rstd = rsqrtf(red[0] * (1.f / Dd) + 1e-5f);
    __syncthreads();
    float rstd = s_rstd;
    float m = mask[row];
    float mm = m * m;
    for (int r = 0; r < 2; r++) {
        int d = tid + r * 256;
        float nv = (x[d] - mean) * rstd * ln_g[d] + ln_b[d];
        out[(size_t)row * Dd + d] = g_attnp[(size_t)row * Dd + d] + nv * mm;
    }
}

// ---------------- launch ----------------
extern "C" void kernel_launch(void* const* d_in, const int* in_sizes, int n_in,
                              void* d_out, int out_size) {
    const float* query  = (const float*)d_in[0];
    const float* key    = (const float*)d_in[1];
    const float* value  = (const float*)d_in[2];
    const float* cross  = (const float*)d_in[3];
    const float* df     = (const float*)d_in[4];
    const float* mask   = (const float*)d_in[5];
    const int*   t_idx  = (const int*)  d_in[6];
    const float* q_r = (const float*)d_in[7],  *q_i = (const float*)d_in[8];
    const float* q_j = (const float*)d_in[9],  *q_k = (const float*)d_in[10];
    const float* q_b = (const float*)d_in[11];
    const float* k_r = (const float*)d_in[12], *k_i = (const float*)d_in[13];
    const float* k_j = (const float*)d_in[14], *k_k = (const float*)d_in[15];
    const float* k_b = (const float*)d_in[16];
    const float* v_w = (const float*)d_in[17], *v_b = (const float*)d_in[18];
    const float* o_w = (const float*)d_in[19], *o_b = (const float*)d_in[20];
    const float* thr = (const float*)d_in[21];
    const float* dm1_w = (const float*)d_in[22], *dm1_b = (const float*)d_in[23];
    const float* dm2_w = (const float*)d_in[24], *dm2_b = (const float*)d_in[25];
    const float* ef  = (const float*)d_in[26], *ec  = (const float*)d_in[27];
    const float* ev_w = (const float*)d_in[28], *ev_b = (const float*)d_in[29];
    const float* ln_g = (const float*)d_in[30], *ln_b = (const float*)d_in[31];
    float* out = (float*)d_out;

    float *pWq, *pWk, *pKsum, *pVcat, *pQ, *pK, *pV, *pAttn, *pAttnP, *pCtx, *pCtx2;
    cudaGetSymbolAddress((void**)&pWq,   g_Wq);
    cudaGetSymbolAddress((void**)&pWk,   g_Wk);
    cudaGetSymbolAddress((void**)&pKsum, g_ksum);
    cudaGetSymbolAddress((void**)&pVcat, g_vcat);
    cudaGetSymbolAddress((void**)&pQ,    g_q);
    cudaGetSymbolAddress((void**)&pK,    g_k);
    cudaGetSymbolAddress((void**)&pV,    g_v);
    cudaGetSymbolAddress((void**)&pAttn, g_attn);
    cudaGetSymbolAddress((void**)&pAttnP,g_attnp);
    cudaGetSymbolAddress((void**)&pCtx,  g_ctx);
    cudaGetSymbolAddress((void**)&pCtx2, g_ctx2);

    // weights + prep + threshold + sort
    build_w_kernel<<<(Dd*Dd + 255) / 256, 256>>>(q_r, q_i, q_j, q_k, pWq);
    build_w_kernel<<<(Dd*Dd + 255) / 256, 256>>>(k_r, k_i, k_j, k_k, pWk);
    prep_kernel<<<2048, 256>>>(key, cross, value);
    thr_kernel<<<(ROWS + 255) / 256, 256>>>(df, dm1_w, dm1_b, dm2_w, dm2_b, thr);
    sort_kernel<<<Bsz, 1024>>>(t_idx);

    // projections (128x128 SGEMM)
    dim3 gp(Dd / 128, ROWS / 128);
    gemm128_kernel<<<gp, 256>>>(query, pWq, q_b, 1.f, pQ, ROWS, Dd, Dd);
    gemm128_kernel<<<gp, 256>>>(pKsum, pWk, k_b, 2.f, pK, ROWS, Dd, Dd);
    gemm128_kernel<<<gp, 256>>>(pVcat, v_w, v_b, 1.f, pV, ROWS, Dd, 2 * Dd);

    // flash attention (fused scores/softmax/PV)
    size_t smem = (4 * 64 * 68 + 3 * 64) * sizeof(float);
    cudaFuncSetAttribute(attn_kernel, cudaFuncAttributeMaxDynamicSharedMemorySize, (int)(smem + 1024));
    attn_kernel<<<Bsz * Hh * (Nn / 64), 256, smem>>>(mask);
    gemm128_kernel<<<gp, 256>>>(pAttn, o_w, o_b, 1.f, pAttnP, ROWS, Dd, Dd);

    // event conv (K=64, 8 rows/block) + event value projection
    event_kernel<<<ROWS / 8, 256>>>(query, mask, ef, ec);
    gemm128_kernel<<<gp, 256>>>(pCtx, ev_w, ev_b, 1.f, pCtx2, ROWS, Dd, Dd);

    // layernorm + combine
    final_kernel<<<ROWS, 256>>>(mask, ln_g, ln_b, out);
}